// round 2
// baseline (speedup 1.0000x reference)
#include <cuda_runtime.h>
#include <cstdint>

// Shapes (fixed):
//   z:     [16, 128, 32, 32] f32   (B=16, C=128=L*D, H=W=32)
//   codes: [8, 512, 16]      f32   (L=8, K=512, D=16)
// d_out (f32): soft[16384*128] | hard[16384*128] | idx[16384*8]

#define KN   512
#define DN   16
#define LN   8
#define NPOS 16384
#define HN   (NPOS * 128)

typedef unsigned long long f2;  // packed f32x2

__device__ __forceinline__ f2 pack2(float lo, float hi) {
    f2 r; asm("mov.b64 %0, {%1,%2};" : "=l"(r) : "f"(lo), "f"(hi)); return r;
}
__device__ __forceinline__ void unpack2(f2 v, float& lo, float& hi) {
    asm("mov.b64 {%0,%1}, %2;" : "=f"(lo), "=f"(hi) : "l"(v));
}
__device__ __forceinline__ f2 mul2(f2 a, f2 b) {
    f2 d; asm("mul.rn.f32x2 %0, %1, %2;" : "=l"(d) : "l"(a), "l"(b)); return d;
}
__device__ __forceinline__ f2 fma2(f2 a, f2 b, f2 c) {
    f2 d; asm("fma.rn.f32x2 %0, %1, %2, %3;" : "=l"(d) : "l"(a), "l"(b), "l"(c)); return d;
}
__device__ __forceinline__ float sqrt_approx(float x) {
    float r; asm("sqrt.approx.f32 %0, %1;" : "=f"(r) : "f"(x)); return r;
}

__global__ __launch_bounds__(256, 2)
void vq_kernel(const float* __restrict__ z,
               const float* __restrict__ codes,
               float* __restrict__ out,
               int out_size)
{
    __shared__ float cs[KN * DN];   // codes[l], row-major [k][d]  (32 KB)
    __shared__ float w2s[KN];       // ||codes[l][k]||^2 (ref-ordered)

    const int l = blockIdx.y;
    const int n = blockIdx.x * blockDim.x + threadIdx.x;
    const int b = n >> 10;
    const int s = n & 1023;

    // ---- cooperative load of codes[l] into smem ----
    {
        const float4* cg = reinterpret_cast<const float4*>(codes + (size_t)l * KN * DN);
        float4* cs4 = reinterpret_cast<float4*>(cs);
        #pragma unroll 4
        for (int i = threadIdx.x; i < KN * DN / 4; i += 256) cs4[i] = cg[i];
    }
    __syncthreads();
    // w2: mul (rounded) then sequential adds — mirrors jnp.sum(codes*codes, -1)
    for (int k = threadIdx.x; k < KN; k += 256) {
        const float* c = cs + k * DN;
        float a = 0.f;
        #pragma unroll
        for (int d = 0; d < DN; d++) a = __fadd_rn(a, __fmul_rn(c[d], c[d]));
        w2s[k] = a;
    }
    __syncthreads();

    // ---- load h: z[b, l*16+d, s], coalesced across threads ----
    const float* zb = z + (size_t)b * (128 * 1024) + (size_t)(l * DN) * 1024 + s;
    float h[DN];
    #pragma unroll
    for (int d = 0; d < DN; d++) h[d] = zb[(size_t)d * 1024];
    // h2: mul then sequential add (ref order)
    float h2 = 0.f;
    #pragma unroll
    for (int d = 0; d < DN; d++) h2 = __fadd_rn(h2, __fmul_rn(h[d], h[d]));

    // ---- main loop: ref-ordered d2 + top-2 argmin + online softmax ----
    float best0 = 3.4e38f, best1 = 3.4e38f;
    int   k0 = 0, k1 = 0;
    float m = 3.4e38f;     // running min dist (approx)
    float S = 0.f;
    f2 acc[8];
    #pragma unroll
    for (int i = 0; i < 8; i++) acc[i] = 0ull;

    const float2* csf = reinterpret_cast<const float2*>(cs);

    #pragma unroll 2
    for (int k = 0; k < KN; k++) {
        float2 q[8];
        #pragma unroll
        for (int i = 0; i < 8; i++) q[i] = csf[k * 8 + i];

        // cross: strictly sequential fmaf chain over d (ref contraction order)
        float dot = 0.f;
        #pragma unroll
        for (int i = 0; i < 8; i++) {
            dot = fmaf(h[2 * i],     q[i].x, dot);
            dot = fmaf(h[2 * i + 1], q[i].y, dot);
        }

        // d2 = (h2 - 2*cross) + w2, left-associated, no contraction
        float t  = __fadd_rn(h2, -__fmul_rn(2.0f, dot));
        float d2 = __fadd_rn(t, w2s[k]);

        // top-2 tracking (strict < keeps first index on exact ties)
        if (d2 < best0)      { best1 = best0; k1 = k0; best0 = d2; k0 = k; }
        else if (d2 < best1) { best1 = d2; k1 = k; }

        // softmax path (loose tolerance): approx sqrt + online rescale
        float dist = sqrt_approx(fmaxf(d2, 1e-12f));
        if (dist < m) {
            float sc = __expf(dist - m);     // first iter: 0
            S *= sc;
            f2 sc2 = pack2(sc, sc);
            #pragma unroll
            for (int i = 0; i < 8; i++) acc[i] = mul2(acc[i], sc2);
            m = dist;
        }
        float w = __expf(m - dist);
        S += w;
        f2 wp = pack2(w, w);
        #pragma unroll
        for (int i = 0; i < 8; i++)
            acc[i] = fma2(wp, pack2(q[i].x, q[i].y), acc[i]);
    }

    // ---- resolve argmin with the reference's sqrt-plateau tie rule ----
    float s0 = __fsqrt_rn(fmaxf(best0, 1e-12f));
    float s1 = __fsqrt_rn(fmaxf(best1, 1e-12f));
    int bk = (s1 == s0 && k1 < k0) ? k1 : k0;

    // ---- epilogue ----
    float inv = 1.0f / S;
    float so[DN];
    #pragma unroll
    for (int i = 0; i < 8; i++) unpack2(acc[i], so[2 * i], so[2 * i + 1]);

    {
        float4* o4 = reinterpret_cast<float4*>(out + (size_t)n * 128 + l * DN);
        #pragma unroll
        for (int j = 0; j < 4; j++) {
            float4 v;
            v.x = so[4 * j + 0] * inv;
            v.y = so[4 * j + 1] * inv;
            v.z = so[4 * j + 2] * inv;
            v.w = so[4 * j + 3] * inv;
            o4[j] = v;
        }
    }
    if (out_size >= 2 * HN) {
        const float4* cr = reinterpret_cast<const float4*>(cs + bk * DN);
        float4* ho = reinterpret_cast<float4*>(out + HN + (size_t)n * 128 + l * DN);
        #pragma unroll
        for (int j = 0; j < 4; j++) ho[j] = cr[j];
    }
    if (out_size >= 2 * HN + NPOS * LN) {
        out[2 * HN + (size_t)n * LN + l] = (float)bk;
    }
}

extern "C" void kernel_launch(void* const* d_in, const int* in_sizes, int n_in,
                              void* d_out, int out_size) {
    const float* z     = (const float*)d_in[0];
    const float* codes = (const float*)d_in[1];
    float* out = (float*)d_out;

    dim3 grid(NPOS / 256, LN);   // (64, 8)
    vq_kernel<<<grid, 256>>>(z, codes, out, out_size);
}

// round 3
// speedup vs baseline: 1.1984x; 1.1984x over previous
#include <cuda_runtime.h>
#include <cstdint>

// Shapes (fixed):
//   z:     [16, 128, 32, 32] f32   (B=16, C=128=L*D, H=W=32)
//   codes: [8, 512, 16]      f32   (L=8, K=512, D=16)
// d_out (f32): soft[16384*128] | hard[16384*128] | idx[16384*8]

#define KN   512
#define DN   16
#define LN   8
#define NPOS 16384
#define HN   (NPOS * 128)

typedef unsigned long long f2;  // packed f32x2

__device__ __forceinline__ f2 pack2(float lo, float hi) {
    f2 r; asm("mov.b64 %0, {%1,%2};" : "=l"(r) : "f"(lo), "f"(hi)); return r;
}
__device__ __forceinline__ void unpack2(f2 v, float& lo, float& hi) {
    asm("mov.b64 {%0,%1}, %2;" : "=f"(lo), "=f"(hi) : "l"(v));
}
__device__ __forceinline__ f2 fma2(f2 a, f2 b, f2 c) {
    f2 d; asm("fma.rn.f32x2 %0, %1, %2, %3;" : "=l"(d) : "l"(a), "l"(b), "l"(c)); return d;
}
__device__ __forceinline__ float sqrt_approx(float x) {
    float r; asm("sqrt.approx.f32 %0, %1;" : "=f"(r) : "f"(x)); return r;
}
__device__ __forceinline__ float exp_approx(float x) {   // e^x via ex2
    float r;
    asm("mul.f32 %0, %1, 0f3FB8AA3B;\n\tex2.approx.f32 %0, %0;" : "=f"(r) : "f"(x));
    return r;
}

// exact d2 in reference order; must be bit-identical between main loop and rescan
__device__ __forceinline__ float d2_exact(const float* __restrict__ h, float h2,
                                          const float* __restrict__ c, float w2) {
    float dot = 0.f;
    #pragma unroll
    for (int d = 0; d < DN; d++) dot = fmaf(h[d], c[d], dot);
    // (h2 - 2*dot) + w2 ; 2*dot is exact, so fmaf(-2,dot,h2) == fl(h2 - fl(2*dot))
    float t = fmaf(-2.0f, dot, h2);
    return __fadd_rn(t, w2);
}

__global__ __launch_bounds__(256, 3)
void vq_kernel(const float* __restrict__ z,
               const float* __restrict__ codes,
               float* __restrict__ out,
               int out_size)
{
    __shared__ __align__(16) float cs[KN * DN];   // codes[l], [k][d], 32 KB
    __shared__ float w2s[KN];                     // ||codes[l][k]||^2 (ref order)

    const int l = blockIdx.y;
    const int n = blockIdx.x * blockDim.x + threadIdx.x;
    const int b = n >> 10;
    const int s = n & 1023;

    // ---- cooperative load of codes[l] ----
    {
        const float4* cg = reinterpret_cast<const float4*>(codes + (size_t)l * KN * DN);
        float4* cs4 = reinterpret_cast<float4*>(cs);
        #pragma unroll 4
        for (int i = threadIdx.x; i < KN * DN / 4; i += 256) cs4[i] = cg[i];
    }
    __syncthreads();
    for (int k = threadIdx.x; k < KN; k += 256) {
        const float* c = cs + k * DN;
        float a = 0.f;
        #pragma unroll
        for (int d = 0; d < DN; d++) a = __fadd_rn(a, __fmul_rn(c[d], c[d]));
        w2s[k] = a;
    }
    __syncthreads();

    // ---- h for this (position, l) ----
    const float* zb = z + (size_t)b * (128 * 1024) + (size_t)(l * DN) * 1024 + s;
    float h[DN];
    #pragma unroll
    for (int d = 0; d < DN; d++) h[d] = zb[(size_t)d * 1024];
    float h2 = 0.f;
    #pragma unroll
    for (int d = 0; d < DN; d++) h2 = __fadd_rn(h2, __fmul_rn(h[d], h[d]));

    // ---- main loop ----
    float best0 = 3.4e38f, best1 = 3.4e38f;
    int   k0 = 0;
    float S = 0.f;
    f2 acc[8];
    #pragma unroll
    for (int i = 0; i < 8; i++) acc[i] = 0ull;

    const float4* q4 = reinterpret_cast<const float4*>(cs);

    #pragma unroll 4
    for (int k = 0; k < KN; k++) {
        float4 qa = q4[k * 4 + 0];
        float4 qb = q4[k * 4 + 1];
        float4 qc = q4[k * 4 + 2];
        float4 qd = q4[k * 4 + 3];

        // exact sequential dot (reference contraction order)
        float dot = 0.f;
        dot = fmaf(h[0],  qa.x, dot); dot = fmaf(h[1],  qa.y, dot);
        dot = fmaf(h[2],  qa.z, dot); dot = fmaf(h[3],  qa.w, dot);
        dot = fmaf(h[4],  qb.x, dot); dot = fmaf(h[5],  qb.y, dot);
        dot = fmaf(h[6],  qb.z, dot); dot = fmaf(h[7],  qb.w, dot);
        dot = fmaf(h[8],  qc.x, dot); dot = fmaf(h[9],  qc.y, dot);
        dot = fmaf(h[10], qc.z, dot); dot = fmaf(h[11], qc.w, dot);
        dot = fmaf(h[12], qd.x, dot); dot = fmaf(h[13], qd.y, dot);
        dot = fmaf(h[14], qd.z, dot); dot = fmaf(h[15], qd.w, dot);

        float t  = fmaf(-2.0f, dot, h2);
        float d2 = __fadd_rn(t, w2s[k]);

        // argmin: first-index best + value-only second best
        float b0_old = best0;
        bool lt0 = d2 < best0;              // strict < keeps first index
        best0 = lt0 ? d2 : best0;
        k0    = lt0 ? k  : k0;
        best1 = fminf(best1, fmaxf(b0_old, d2));

        // softmax path (loose tolerance): no rescaling needed, dist >= 0
        float dist = sqrt_approx(fmaxf(d2, 1e-12f));
        float w = exp_approx(-dist);        // <= 1, >= ~3e-7 for this data
        S += w;
        f2 wp = pack2(w, w);
        acc[0] = fma2(wp, pack2(qa.x, qa.y), acc[0]);
        acc[1] = fma2(wp, pack2(qa.z, qa.w), acc[1]);
        acc[2] = fma2(wp, pack2(qb.x, qb.y), acc[2]);
        acc[3] = fma2(wp, pack2(qb.z, qb.w), acc[3]);
        acc[4] = fma2(wp, pack2(qc.x, qc.y), acc[4]);
        acc[5] = fma2(wp, pack2(qc.z, qc.w), acc[5]);
        acc[6] = fma2(wp, pack2(qd.x, qd.y), acc[6]);
        acc[7] = fma2(wp, pack2(qd.z, qd.w), acc[7]);
    }

    // ---- resolve argmin with reference sqrt-plateau tie rule ----
    float s0 = __fsqrt_rn(fmaxf(best0, 1e-12f));
    float s1 = __fsqrt_rn(fmaxf(best1, 1e-12f));
    int bk = k0;
    if (s1 == s0) {
        // plateau tie (rare): first index whose ref fp32 distance equals s0
        for (int k = 0; k < KN; k++) {
            float d2 = d2_exact(h, h2, cs + k * DN, w2s[k]);
            if (__fsqrt_rn(fmaxf(d2, 1e-12f)) == s0) { bk = k; break; }
        }
    }

    // ---- epilogue ----
    float inv = 1.0f / S;
    float so[DN];
    #pragma unroll
    for (int i = 0; i < 8; i++) unpack2(acc[i], so[2 * i], so[2 * i + 1]);

    {
        float4* o4 = reinterpret_cast<float4*>(out + (size_t)n * 128 + l * DN);
        #pragma unroll
        for (int j = 0; j < 4; j++) {
            float4 v;
            v.x = so[4 * j + 0] * inv;
            v.y = so[4 * j + 1] * inv;
            v.z = so[4 * j + 2] * inv;
            v.w = so[4 * j + 3] * inv;
            o4[j] = v;
        }
    }
    if (out_size >= 2 * HN) {
        const float4* cr = reinterpret_cast<const float4*>(cs + bk * DN);
        float4* ho = reinterpret_cast<float4*>(out + HN + (size_t)n * 128 + l * DN);
        #pragma unroll
        for (int j = 0; j < 4; j++) ho[j] = cr[j];
    }
    if (out_size >= 2 * HN + NPOS * LN) {
        out[2 * HN + (size_t)n * LN + l] = (float)bk;
    }
}

extern "C" void kernel_launch(void* const* d_in, const int* in_sizes, int n_in,
                              void* d_out, int out_size) {
    const float* z     = (const float*)d_in[0];
    const float* codes = (const float*)d_in[1];
    float* out = (float*)d_out;

    dim3 grid(NPOS / 256, LN);   // (64, 8)
    vq_kernel<<<grid, 256>>>(z, codes, out, out_size);
}